// round 5
// baseline (speedup 1.0000x reference)
#include <cuda_runtime.h>
#include <cuda_bf16.h>

#define HH 1024
#define WW 1024
#define NB 8

typedef unsigned long long u64;

// ---- packed fp32x2 helpers (sm_103a FFMA2 path, PTX-only) ----
__device__ __forceinline__ u64 pk(float lo, float hi) {
    u64 r; asm("mov.b64 %0, {%1, %2};" : "=l"(r) : "f"(lo), "f"(hi)); return r;
}
__device__ __forceinline__ void upk(u64 v, float& lo, float& hi) {
    asm("mov.b64 {%0, %1}, %2;" : "=f"(lo), "=f"(hi) : "l"(v));
}
__device__ __forceinline__ u64 fma2(u64 a, u64 b, u64 c) {
    u64 d; asm("fma.rn.f32x2 %0, %1, %2, %3;" : "=l"(d) : "l"(a), "l"(b), "l"(c));
    return d;
}

// Load the 4-wide window (cols w0-1 .. w0+2) of row hh as 3 sliding f32x2
// pairs: p[c] = (win[c], win[c+1]). The aligned LDG.64 at w0 IS pair p[1];
// only the two edge scalars need packing. All 3 loads independent (MLP).
__device__ __forceinline__ void load_row_pairs(const float* __restrict__ base,
                                               int hh, int w0, u64 p[3]) {
    if (hh < 0 || hh >= HH) { p[0] = p[1] = p[2] = 0ull; return; }
    const float* row = base + (size_t)hh * WW;
    float2 f = *reinterpret_cast<const float2*>(row + w0);
    float e0 = (w0 > 0)       ? row[w0 - 1] : 0.0f;
    float e3 = (w0 + 2 < WW)  ? row[w0 + 2] : 0.0f;
    p[0] = pk(e0, f.x);
    p[1] = pk(f.x, f.y);   // register-pair alias of the LDG.64 result
    p[2] = pk(f.y, e3);
}

__global__ void __launch_bounds__(128, 6)
small_sm_block_kernel(const float* __restrict__ image,
                      const float* __restrict__ x,
                      const float* __restrict__ wgt,   // (9,1,3,3) = 81
                      const float* __restrict__ bias,  // (9,)
                      float* __restrict__ y) {
    __shared__ u64 sw2[81];
    __shared__ u64 sb2[9];
    int t = threadIdx.x;
    if (t < 81) { float w = wgt[t];  sw2[t] = pk(w, w); }
    if (t < 9)  { float b = bias[t]; sb2[t] = pk(b, b); }
    __syncthreads();

    const int h0 = blockIdx.y * 2;                            // rows h0, h0+1
    const int w0 = (blockIdx.x * blockDim.x + t) * 2;         // cols w0, w0+1

    // ---- image window: 4 rows (h0-1..h0+2) x 4 cols as sliding pairs ----
    u64 ip[4][3];
#pragma unroll
    for (int r = 0; r < 4; r++) load_row_pairs(image, h0 - 1 + r, w0, ip[r]);

    // ---- per-pixel kernels, packed over the 2 columns:
    //      KA[j] = (K[j] @ (h0,w0),   K[j] @ (h0,w0+1))
    //      KB[j] = (K[j] @ (h0+1,w0), K[j] @ (h0+1,w0+1)) ----
    u64 KA[9], KB[9];
#pragma unroll
    for (int j = 0; j < 9; j++) {
        u64 b2 = sb2[j];
        KA[j] = b2; KB[j] = b2;
#pragma unroll
        for (int a = 0; a < 3; a++)
#pragma unroll
            for (int d = 0; d < 3; d++) {
                u64 w2 = sw2[j * 9 + a * 3 + d];
                KA[j] = fma2(ip[a][d],     w2, KA[j]);
                KB[j] = fma2(ip[a + 1][d], w2, KB[j]);
            }
    }

    // ---- apply: 4 x-rows serve 2 output rows, packed over 2 columns ----
    const size_t plane = (size_t)HH * WW;
    const size_t o0 = (size_t)h0 * WW + w0;
#pragma unroll
    for (int b = 0; b < NB; b++) {
        const float* xb = x + (size_t)b * plane;
        u64 xp[4][3];
#pragma unroll
        for (int r = 0; r < 4; r++) load_row_pairs(xb, h0 - 1 + r, w0, xp[r]);

        u64 accA = 0ull, accB = 0ull;   // (+0.f, +0.f)
#pragma unroll
        for (int a = 0; a < 3; a++)
#pragma unroll
            for (int d = 0; d < 3; d++) {
                const int j = a * 3 + d;
                accA = fma2(xp[a][d],     KA[j], accA);
                accB = fma2(xp[a + 1][d], KB[j], accB);
            }

        u64* yA = reinterpret_cast<u64*>(y + (size_t)b * plane + o0);
        u64* yB = reinterpret_cast<u64*>(y + (size_t)b * plane + o0 + WW);
        *yA = accA;
        *yB = accB;
    }
}

extern "C" void kernel_launch(void* const* d_in, const int* in_sizes, int n_in,
                              void* d_out, int out_size) {
    const float* image = (const float*)d_in[0];  // (1, 1024, 1024)
    const float* x     = (const float*)d_in[1];  // (8, 1, 1024, 1024)
    const float* klw   = (const float*)d_in[2];  // (9, 1, 3, 3)
    const float* klb   = (const float*)d_in[3];  // (9,)
    float* y = (float*)d_out;                    // (8, 1, 1024, 1024)

    dim3 block(128);
    dim3 grid(WW / 2 / 128, HH / 2);  // (4, 512)
    small_sm_block_kernel<<<grid, block>>>(image, x, klw, klb, y);
}

// round 6
// speedup vs baseline: 1.0620x; 1.0620x over previous
#include <cuda_runtime.h>
#include <cuda_bf16.h>

#define HH 1024
#define WW 1024
#define NB 8

typedef unsigned long long u64;

// ---- packed fp32x2 helpers (sm_103a FFMA2 path, PTX-only) ----
__device__ __forceinline__ u64 pk(float lo, float hi) {
    u64 r; asm("mov.b64 %0, {%1, %2};" : "=l"(r) : "f"(lo), "f"(hi)); return r;
}
__device__ __forceinline__ u64 fma2(u64 a, u64 b, u64 c) {
    u64 d; asm("fma.rn.f32x2 %0, %1, %2, %3;" : "=l"(d) : "l"(a), "l"(b), "l"(c));
    return d;
}

// Load the 6-wide window (cols w0-1 .. w0+4) of row hh as 5 sliding f32x2
// pairs p[c] = (win[c], win[c+1]). One aligned LDG.128 + two predicated edge
// scalars, all independent (keep MLP high — R2 showed shuffles are toxic).
// Pairs p[1] = (v.x,v.y) and p[3] = (v.z,v.w) are free; p[0], p[2], p[4] are
// one MOV64 pack each.
__device__ __forceinline__ void load_row_pairs(const float* __restrict__ base,
                                               int hh, int w0, u64 p[5]) {
    if (hh < 0 || hh >= HH) {
#pragma unroll
        for (int c = 0; c < 5; c++) p[c] = 0ull;
        return;
    }
    const float* row = base + (size_t)hh * WW;
    float4 v = *reinterpret_cast<const float4*>(row + w0);
    float e0 = (w0 > 0)       ? row[w0 - 1] : 0.0f;
    float e5 = (w0 + 4 < WW)  ? row[w0 + 4] : 0.0f;
    p[0] = pk(e0, v.x);
    p[1] = pk(v.x, v.y);   // register-pair alias
    p[2] = pk(v.y, v.z);
    p[3] = pk(v.z, v.w);   // register-pair alias
    p[4] = pk(v.w, e5);
}

__global__ void __launch_bounds__(128, 6)
small_sm_block_kernel(const float* __restrict__ image,
                      const float* __restrict__ x,
                      const float* __restrict__ wgt,   // (9,1,3,3) = 81
                      const float* __restrict__ bias,  // (9,)
                      float* __restrict__ y) {
    __shared__ u64 sw2[81];
    __shared__ u64 sb2[9];
    int t = threadIdx.x;
    if (t < 81) { float w = wgt[t];  sw2[t] = pk(w, w); }
    if (t < 9)  { float b = bias[t]; sb2[t] = pk(b, b); }
    __syncthreads();

    const int h  = blockIdx.y;                        // one output row
    const int w0 = (blockIdx.x * blockDim.x + t) * 4; // 4 output cols

    // ---- image window: 3 rows x 6 cols as sliding pairs ----
    u64 ip[3][5];
#pragma unroll
    for (int r = 0; r < 3; r++) load_row_pairs(image, h - 1 + r, w0, ip[r]);

    // ---- per-pixel kernels, packed over 4 cols:
    //      K01[j] = (K[j]@(h,w0),   K[j]@(h,w0+1))
    //      K23[j] = (K[j]@(h,w0+2), K[j]@(h,w0+3)) ----
    u64 K01[9], K23[9];
#pragma unroll
    for (int j = 0; j < 9; j++) {
        u64 b2 = sb2[j];
        K01[j] = b2; K23[j] = b2;
#pragma unroll
        for (int a = 0; a < 3; a++)
#pragma unroll
            for (int d = 0; d < 3; d++) {
                u64 w2 = sw2[j * 9 + a * 3 + d];
                K01[j] = fma2(ip[a][d],     w2, K01[j]);
                K23[j] = fma2(ip[a][d + 2], w2, K23[j]);
            }
    }

    // ---- apply across batches (3 x-rows per batch, 1 output row) ----
    const size_t plane = (size_t)HH * WW;
    const size_t o0 = (size_t)h * WW + w0;
#pragma unroll 2
    for (int b = 0; b < NB; b++) {
        const float* xb = x + (size_t)b * plane;
        u64 xp[3][5];
#pragma unroll
        for (int r = 0; r < 3; r++) load_row_pairs(xb, h - 1 + r, w0, xp[r]);

        u64 a01 = 0ull, a23 = 0ull;   // (+0.f, +0.f)
#pragma unroll
        for (int a = 0; a < 3; a++)
#pragma unroll
            for (int d = 0; d < 3; d++) {
                const int j = a * 3 + d;
                a01 = fma2(xp[a][d],     K01[j], a01);
                a23 = fma2(xp[a][d + 2], K23[j], a23);
            }

        // store 4 floats = 2x 64-bit (a01, a23 are already (y0,y1),(y2,y3))
        u64* yo = reinterpret_cast<u64*>(y + (size_t)b * plane + o0);
        yo[0] = a01;
        yo[1] = a23;
    }
}

extern "C" void kernel_launch(void* const* d_in, const int* in_sizes, int n_in,
                              void* d_out, int out_size) {
    const float* image = (const float*)d_in[0];  // (1, 1024, 1024)
    const float* x     = (const float*)d_in[1];  // (8, 1, 1024, 1024)
    const float* klw   = (const float*)d_in[2];  // (9, 1, 3, 3)
    const float* klb   = (const float*)d_in[3];  // (9,)
    float* y = (float*)d_out;                    // (8, 1, 1024, 1024)

    dim3 block(128);
    dim3 grid(WW / 4 / 128, HH);  // (2, 1024)
    small_sm_block_kernel<<<grid, block>>>(image, x, klw, klb, y);
}